// round 2
// baseline (speedup 1.0000x reference)
#include <cuda_runtime.h>
#include <math.h>
#include <stdint.h>

// Problem constants
#define BB  2
#define SS  4096
#define DDIM 1024
#define HH  16
#define DHH 64
#define MM  (BB*SS)   // 8192 rows

// Scratch (allocation-free rule: __device__ globals)
__device__ float g_Q[MM*DDIM];
__device__ float g_K[MM*DDIM];
__device__ float g_V[MM*DDIM];
__device__ float g_ctx[MM*DDIM];

// ---------------------------------------------------------------------------
// SGEMM: C[M,1024] = A[M,1024] @ W[1024,1024] (+bias). 128x128 tile, BK=8,
// 256 threads, 8x8 register tile per thread.
// ---------------------------------------------------------------------------
__device__ __forceinline__ void sgemm_body(const float* __restrict__ A,
                                           const float* __restrict__ W,
                                           float* __restrict__ C,
                                           const float* __restrict__ bias)
{
    __shared__ float As[8][128];
    __shared__ float Bs[8][128];

    const int tid = threadIdx.x;
    const int m0  = blockIdx.y * 128;
    const int n0  = blockIdx.x * 128;
    const int tx  = tid & 15;        // col group
    const int ty  = tid >> 4;        // row group
    const int a_row = tid >> 1;          // 0..127
    const int a_col = (tid & 1) << 2;    // 0 or 4
    const int b_row = tid >> 5;          // 0..7
    const int b_col = (tid & 31) << 2;   // 0..124

    const float* Ap = A + (size_t)(m0 + a_row) * DDIM + a_col;
    const float* Wp = W + (size_t)b_row * DDIM + n0 + b_col;

    float acc[8][8];
#pragma unroll
    for (int i = 0; i < 8; i++)
#pragma unroll
        for (int j = 0; j < 8; j++) acc[i][j] = 0.f;

    for (int k0 = 0; k0 < DDIM; k0 += 8) {
        float4 av = *(const float4*)(Ap + k0);
        float4 bv = *(const float4*)(Wp + (size_t)k0 * DDIM);
        As[a_col + 0][a_row] = av.x;
        As[a_col + 1][a_row] = av.y;
        As[a_col + 2][a_row] = av.z;
        As[a_col + 3][a_row] = av.w;
        *(float4*)&Bs[b_row][b_col] = bv;
        __syncthreads();

#pragma unroll
        for (int kk = 0; kk < 8; kk++) {
            float ra[8], rb[8];
            *(float4*)&ra[0] = *(const float4*)&As[kk][ty * 8];
            *(float4*)&ra[4] = *(const float4*)&As[kk][ty * 8 + 4];
            *(float4*)&rb[0] = *(const float4*)&Bs[kk][tx * 8];
            *(float4*)&rb[4] = *(const float4*)&Bs[kk][tx * 8 + 4];
#pragma unroll
            for (int i = 0; i < 8; i++)
#pragma unroll
                for (int j = 0; j < 8; j++)
                    acc[i][j] = fmaf(ra[i], rb[j], acc[i][j]);
        }
        __syncthreads();
    }

#pragma unroll
    for (int i = 0; i < 8; i++) {
        float* cp = C + (size_t)(m0 + ty * 8 + i) * DDIM + n0 + tx * 8;
#pragma unroll
        for (int j = 0; j < 8; j += 4) {
            float4 v = make_float4(acc[i][j], acc[i][j+1], acc[i][j+2], acc[i][j+3]);
            if (bias != nullptr) {
                const float* bp = bias + n0 + tx * 8 + j;
                v.x += bp[0]; v.y += bp[1]; v.z += bp[2]; v.w += bp[3];
            }
            *(float4*)(cp + j) = v;
        }
    }
}

__global__ __launch_bounds__(256) void qkv_gemm_kernel(const float* __restrict__ x,
                                                       const float* __restrict__ Wq,
                                                       const float* __restrict__ Wk,
                                                       const float* __restrict__ Wv)
{
    const float* W = (blockIdx.z == 0) ? Wq : (blockIdx.z == 1) ? Wk : Wv;
    float* C       = (blockIdx.z == 0) ? g_Q : (blockIdx.z == 1) ? g_K : g_V;
    sgemm_body(x, W, C, nullptr);
}

__global__ __launch_bounds__(256) void out_gemm_kernel(const float* __restrict__ Wo,
                                                       const float* __restrict__ bo,
                                                       float* __restrict__ out)
{
    sgemm_body(g_ctx, Wo, out, bo);
}

// ---------------------------------------------------------------------------
// Causal flash attention. One CTA = 64 queries x one (b,h). 256 threads.
// Scores + PV via 4x4 register tiles (rank-1 updates).
// smem: Qt (d-major, swizzled), KtPs (K d-major, later aliased as P k-major),
//       Vs (k-major). 3 x 16KB = 48KB static.
// Swizzle for d-major [64][64] arrays: elem (row r, col q) at
//   r*64 + (((q>>2 + r) & 15) << 2) + (q & 3)   -> conflict-free f4 reads.
// ---------------------------------------------------------------------------
#define NEG_BIG (-1e30f)

__global__ __launch_bounds__(256) void attn_kernel()
{
    __shared__ float Qt[64 * 64];
    __shared__ float KtPs[64 * 64];
    __shared__ float Vs[64 * 64];

    const int tid = threadIdx.x;
    const int bh  = blockIdx.y;          // b*H + h
    const int b   = bh >> 4;
    const int h   = bh & 15;
    const int qb  = (int)gridDim.x - 1 - (int)blockIdx.x;  // heavy blocks first
    const int q0  = qb * 64;
    const int tq  = tid >> 4;            // 0..15 : q rows tq*4..tq*4+3
    const int tk  = tid & 15;            // 0..15 : k (or d) cols tk*4..tk*4+3
    const int lr  = tid >> 2;            // loader row 0..63
    const int lc  = (tid & 3) << 4;      // loader col base 0/16/32/48
    const int lg  = lr >> 2;             // loader q-group
    const int lq  = lr & 3;              // loader q-in-group

    // Load Q tile: scale by 1/sqrt(DH)=0.125 folded in; transpose to d-major.
    {
        const float* qp = g_Q + (size_t)(b * SS + q0 + lr) * DDIM + h * DHH;
#pragma unroll
        for (int i = 0; i < 4; i++) {
            const int d = lc + 4 * i;
            float4 v = *(const float4*)(qp + d);
            Qt[(d+0)*64 + (((lg + d+0) & 15) << 2) + lq] = v.x * 0.125f;
            Qt[(d+1)*64 + (((lg + d+1) & 15) << 2) + lq] = v.y * 0.125f;
            Qt[(d+2)*64 + (((lg + d+2) & 15) << 2) + lq] = v.z * 0.125f;
            Qt[(d+3)*64 + (((lg + d+3) & 15) << 2) + lq] = v.w * 0.125f;
        }
    }

    float m_i[4], l_i[4], o[4][4];
#pragma unroll
    for (int i = 0; i < 4; i++) {
        m_i[i] = NEG_BIG; l_i[i] = 0.f;
#pragma unroll
        for (int j = 0; j < 4; j++) o[i][j] = 0.f;
    }

    for (int kb = 0; kb <= qb; kb++) {
        const int k0 = kb * 64;

        __syncthreads();   // previous PV done (also orders Qt stores on iter 0)
        // Load K (transposed d-major, swizzled) and V (k-major)
        {
            const float* kp = g_K + (size_t)(b * SS + k0 + lr) * DDIM + h * DHH;
            const float* vp = g_V + (size_t)(b * SS + k0 + lr) * DDIM + h * DHH;
#pragma unroll
            for (int i = 0; i < 4; i++) {
                const int d = lc + 4 * i;
                float4 kv = *(const float4*)(kp + d);
                KtPs[(d+0)*64 + (((lg + d+0) & 15) << 2) + lq] = kv.x;
                KtPs[(d+1)*64 + (((lg + d+1) & 15) << 2) + lq] = kv.y;
                KtPs[(d+2)*64 + (((lg + d+2) & 15) << 2) + lq] = kv.z;
                KtPs[(d+3)*64 + (((lg + d+3) & 15) << 2) + lq] = kv.w;
                float4 vv = *(const float4*)(vp + d);
                *(float4*)&Vs[lr * 64 + d] = vv;
            }
        }
        __syncthreads();

        // Phase A: scores S[4q][4k] = (Q*0.125) . K
        float sacc[4][4];
#pragma unroll
        for (int i = 0; i < 4; i++)
#pragma unroll
            for (int j = 0; j < 4; j++) sacc[i][j] = 0.f;

#pragma unroll 8
        for (int d = 0; d < 64; d++) {
            float4 qv = *(const float4*)&Qt[d * 64 + (((tq + d) & 15) << 2)];
            float4 kv = *(const float4*)&KtPs[d * 64 + (((tk + d) & 15) << 2)];
            float qr[4] = {qv.x, qv.y, qv.z, qv.w};
            float kr[4] = {kv.x, kv.y, kv.z, kv.w};
#pragma unroll
            for (int i = 0; i < 4; i++)
#pragma unroll
                for (int j = 0; j < 4; j++)
                    sacc[i][j] = fmaf(qr[i], kr[j], sacc[i][j]);
        }

        if (kb == qb) {  // diagonal block: causal mask (k > q)
#pragma unroll
            for (int i = 0; i < 4; i++)
#pragma unroll
                for (int j = 0; j < 4; j++)
                    if (tk * 4 + j > tq * 4 + i) sacc[i][j] = NEG_BIG;
        }

        __syncthreads();   // everyone done reading K before P overwrites it

        // Online softmax; write P into KtPs (k-major, swizzled)
#pragma unroll
        for (int i = 0; i < 4; i++) {
            float rmax = fmaxf(fmaxf(sacc[i][0], sacc[i][1]),
                               fmaxf(sacc[i][2], sacc[i][3]));
#pragma unroll
            for (int off = 8; off >= 1; off >>= 1)
                rmax = fmaxf(rmax, __shfl_xor_sync(0xffffffffu, rmax, off));
            const float mnew = fmaxf(m_i[i], rmax);
            const float corr = __expf(m_i[i] - mnew);
            m_i[i] = mnew;
            float p[4]; float rsum = 0.f;
#pragma unroll
            for (int j = 0; j < 4; j++) { p[j] = __expf(sacc[i][j] - mnew); rsum += p[j]; }
#pragma unroll
            for (int off = 8; off >= 1; off >>= 1)
                rsum += __shfl_xor_sync(0xffffffffu, rsum, off);
            l_i[i] = l_i[i] * corr + rsum;
#pragma unroll
            for (int j = 0; j < 4; j++) {
                o[i][j] *= corr;
                const int k = tk * 4 + j;
                KtPs[k * 64 + (((tq + k) & 15) << 2) + i] = p[j];
            }
        }
        __syncthreads();

        // Phase B: O[4q][4d] += P[64k] x V
#pragma unroll 8
        for (int k = 0; k < 64; k++) {
            float4 pv = *(const float4*)&KtPs[k * 64 + (((tq + k) & 15) << 2)];
            float4 vv = *(const float4*)&Vs[k * 64 + (tk << 2)];
            float pr[4] = {pv.x, pv.y, pv.z, pv.w};
            float vr[4] = {vv.x, vv.y, vv.z, vv.w};
#pragma unroll
            for (int i = 0; i < 4; i++)
#pragma unroll
                for (int j = 0; j < 4; j++)
                    o[i][j] = fmaf(pr[i], vr[j], o[i][j]);
        }
    }

    // Epilogue: normalize and write ctx in [b, s, h*64+d] layout
#pragma unroll
    for (int i = 0; i < 4; i++) {
        const float inv = 1.f / l_i[i];
        float4 v = make_float4(o[i][0]*inv, o[i][1]*inv, o[i][2]*inv, o[i][3]*inv);
        *(float4*)(g_ctx + (size_t)(b * SS + q0 + tq * 4 + i) * DDIM + h * DHH + tk * 4) = v;
    }
}

// ---------------------------------------------------------------------------
extern "C" void kernel_launch(void* const* d_in, const int* in_sizes, int n_in,
                              void* d_out, int out_size)
{
    (void)in_sizes; (void)n_in; (void)out_size;
    const float* x  = (const float*)d_in[0];
    const float* Wq = (const float*)d_in[1];
    const float* Wk = (const float*)d_in[2];
    const float* Wv = (const float*)d_in[3];
    const float* Wo = (const float*)d_in[4];
    const float* bo = (const float*)d_in[5];
    float* out = (float*)d_out;

    dim3 gq(DDIM / 128, MM / 128, 3);      // 8 x 64 x 3
    qkv_gemm_kernel<<<gq, 256>>>(x, Wq, Wk, Wv);

    dim3 ga(SS / 64, BB * HH);             // 64 x 32
    attn_kernel<<<ga, 256>>>();

    dim3 go(DDIM / 128, MM / 128);         // 8 x 64
    out_gemm_kernel<<<go, 256>>>(Wo, bo, out);
}

// round 4
// speedup vs baseline: 1.4548x; 1.4548x over previous
#include <cuda_runtime.h>
#include <math.h>
#include <stdint.h>

// Problem constants
#define BB  2
#define SS  4096
#define DDIM 1024
#define HH  16
#define DHH 64
#define MM  (BB*SS)   // 8192 rows

// Scratch (allocation-free rule: __device__ globals)
__device__ float g_x[MM*DDIM];                 // tf32-rounded x
__device__ float g_Wt[4u*DDIM*DDIM];           // tf32-rounded W^T (q,k,v,o)
__device__ float g_Q[MM*DDIM];
__device__ float g_K[MM*DDIM];
__device__ float g_V[MM*DDIM];
__device__ float g_ctx[MM*DDIM];

__device__ __forceinline__ float rna_tf32(float x) {
    uint32_t u;
    asm("cvt.rna.tf32.f32 %0, %1;" : "=r"(u) : "f"(x));
    return __uint_as_float(u);
}

// ===========================================================================
// Pre-pass kernels: tf32 RNA rounding (+ transpose for weights)
// ===========================================================================
__global__ __launch_bounds__(256) void round_x_kernel(const float* __restrict__ x)
{
    const size_t i = ((size_t)blockIdx.x * 256 + threadIdx.x) * 4;
    float4 v = *(const float4*)(x + i);
    v.x = rna_tf32(v.x); v.y = rna_tf32(v.y);
    v.z = rna_tf32(v.z); v.w = rna_tf32(v.w);
    *(float4*)(g_x + i) = v;
}

__global__ __launch_bounds__(256) void transpose_round_kernel(
    const float* __restrict__ Wq, const float* __restrict__ Wk,
    const float* __restrict__ Wv, const float* __restrict__ Wo)
{
    __shared__ float t[32][33];
    const int z = blockIdx.z;
    const float* W = (z == 0) ? Wq : (z == 1) ? Wk : (z == 2) ? Wv : Wo;
    float* Wt = g_Wt + (size_t)z * DDIM * DDIM;
    const int x0 = blockIdx.x * 32, y0 = blockIdx.y * 32;
    const int tx = threadIdx.x, ty = threadIdx.y;   // block (32,8)
#pragma unroll
    for (int i = 0; i < 4; i++) {
        const int row = ty + i * 8;
        t[row][tx] = W[(size_t)(y0 + row) * DDIM + x0 + tx];
    }
    __syncthreads();
#pragma unroll
    for (int i = 0; i < 4; i++) {
        const int row = ty + i * 8;
        Wt[(size_t)(x0 + row) * DDIM + y0 + tx] = rna_tf32(t[tx][row]);
    }
}

// ===========================================================================
// tf32 mma.sync GEMM: C[8192,1024] = A[8192,1024] @ Bt^T   (Bt is [n][k])
// CTA tile 128x128, BK=32, 256 threads = 8 warps (2x4), warp tile 64x32.
// smem staged in mma-fragment order: A frag block = 32 lanes x 4 regs
// (LDS.128 per fragment), B frag block = 32 lanes x 2 regs (LDS.64).
// XOR-ks swizzle on lane position for conflict-free STS.
// Double buffer + register prefetch. 64KB dynamic smem.
// ===========================================================================
#define GTM 128
#define GTN 128
#define GTK 32
#define STG_FLOATS 8192                 // per stage: A 4096 + B 4096
#define GEMM_SMEM_BYTES (2 * STG_FLOATS * 4)   // 65536

#define MMA_TF32(c, a0, a1, a2, a3, b0, b1)                                    \
    asm volatile(                                                              \
        "mma.sync.aligned.m16n8k8.row.col.f32.tf32.tf32.f32 "                  \
        "{%0,%1,%2,%3},{%4,%5,%6,%7},{%8,%9},{%0,%1,%2,%3};"                   \
        : "+f"((c)[0]), "+f"((c)[1]), "+f"((c)[2]), "+f"((c)[3])               \
        : "r"(a0), "r"(a1), "r"(a2), "r"(a3), "r"(b0), "r"(b1))

__device__ __forceinline__ void gemm_mma_body(const float* __restrict__ A,
                                              const float* __restrict__ Bt,
                                              float* __restrict__ C,
                                              const float* __restrict__ bias)
{
    extern __shared__ float sm[];
    const int tid  = threadIdx.x;
    const int lane = tid & 31;
    const int warp = tid >> 5;
    const int wm   = warp >> 2;          // 0..1
    const int wn   = warp & 3;           // 0..3
    const int m0   = blockIdx.y * GTM;
    const int n0   = blockIdx.x * GTN;

    // ---- staging constants (per thread) ----
    const int sr   = tid >> 3;           // base row 0..31 (row = i*32 + sr)
    const int kq   = tid & 7;            // which float4 along k-chunk
    const int ks_s = kq >> 1;            // kstep 0..3
    const int half = kq & 1;             // low/high 4 of the kstep
    const int g_s  = sr & 7;             // fragment group row
    const int hi   = (sr >> 3) & 1;      // (row%16) >= 8
    const int mtb  = sr >> 4;            // m-tile base (0/1); mt = i*2 + mtb
    const int ntb  = sr >> 3;            // nt = i*4 + ntb
    // lane positions with XOR-ks swizzle, element e: g_s*4 + (e^ks_s)
    const int le0 = g_s * 4 + (0 ^ ks_s);
    const int le1 = g_s * 4 + (1 ^ ks_s);
    const int le2 = g_s * 4 + (2 ^ ks_s);
    const int le3 = g_s * 4 + (3 ^ ks_s);

    const float* ga = A  + (size_t)(m0 + sr) * DDIM + kq * 4;
    const float* gb = Bt + (size_t)(n0 + sr) * DDIM + kq * 4;

    float acc[16][4];
#pragma unroll
    for (int t = 0; t < 16; t++)
#pragma unroll
        for (int e = 0; e < 4; e++) acc[t][e] = 0.f;

    float4 ra[4], rb[4];

#define LDG_CHUNK(kc)                                                          \
    {                                                                          \
        _Pragma("unroll")                                                      \
        for (int i = 0; i < 4; i++) {                                          \
            ra[i] = *(const float4*)(ga + (size_t)(i * 32) * DDIM + (kc));     \
            rb[i] = *(const float4*)(gb + (size_t)(i * 32) * DDIM + (kc));     \
        }                                                                      \
    }

#define STS_CHUNK(s)                                                           \
    {                                                                          \
        float* sAp = sm + (s) * STG_FLOATS;                                    \
        float* sBp = sAp + 4096;                                               \
        _Pragma("unroll")                                                      \
        for (int i = 0; i < 4; i++) {                                          \
            float* da = sAp + (ks_s * 8 + i * 2 + mtb) * 128 + half * 2 + hi;  \
            da[le0 * 4] = ra[i].x;                                             \
            da[le1 * 4] = ra[i].y;                                             \
            da[le2 * 4] = ra[i].z;                                             \
            da[le3 * 4] = ra[i].w;                                             \
            float* db = sBp + (ks_s * 16 + i * 4 + ntb) * 64 + half;           \
            db[le0 * 2] = rb[i].x;                                             \
            db[le1 * 2] = rb[i].y;                                             \
            db[le2 * 2] = rb[i].z;                                             \
            db[le3 * 2] = rb[i].w;                                             \
        }                                                                      \
    }

    LDG_CHUNK(0);
    STS_CHUNK(0);
    __syncthreads();

    for (int it = 0; it < 32; ++it) {
        if (it < 31) LDG_CHUNK((it + 1) * GTK);

        const float* sAc = sm + (it & 1) * STG_FLOATS;
        const float* sBc = sAc + 4096;

#pragma unroll
        for (int ks = 0; ks < 4; ks++) {
            const int lsw = lane ^ ks;
            uint32_t af[4][4];
            uint32_t bf[4][2];
#pragma unroll
            for (int i = 0; i < 4; i++) {
                float4 av = *(const float4*)&sAc[((ks * 8 + wm * 4 + i) * 32 + lsw) * 4];
                af[i][0] = __float_as_uint(av.x);
                af[i][1] = __float_as_uint(av.y);
                af[i][2] = __float_as_uint(av.z);
                af[i][3] = __float_as_uint(av.w);
            }
#pragma unroll
            for (int j = 0; j < 4; j++) {
                float2 bv = *(const float2*)&sBc[((ks * 16 + wn * 4 + j) * 32 + lsw) * 2];
                bf[j][0] = __float_as_uint(bv.x);
                bf[j][1] = __float_as_uint(bv.y);
            }
#pragma unroll
            for (int i = 0; i < 4; i++)
#pragma unroll
                for (int j = 0; j < 4; j++)
                    MMA_TF32(acc[i * 4 + j],
                             af[i][0], af[i][1], af[i][2], af[i][3],
                             bf[j][0], bf[j][1]);
        }

        if (it < 31) STS_CHUNK((it + 1) & 1);
        __syncthreads();
    }

    // Epilogue: c0=(g,2c) c1=(g,2c+1) c2=(g+8,2c) c3=(g+8,2c+1)
    const int g   = lane >> 2;
    const int cth = lane & 3;
#pragma unroll
    for (int i = 0; i < 4; i++) {
        const int row = m0 + wm * 64 + i * 16 + g;
#pragma unroll
        for (int j = 0; j < 4; j++) {
            const int col = n0 + wn * 32 + j * 8 + cth * 2;
            float2 v0 = make_float2(acc[i * 4 + j][0], acc[i * 4 + j][1]);
            float2 v1 = make_float2(acc[i * 4 + j][2], acc[i * 4 + j][3]);
            if (bias != nullptr) {
                const float b0 = bias[col], b1 = bias[col + 1];
                v0.x += b0; v0.y += b1;
                v1.x += b0; v1.y += b1;
            }
            *(float2*)&C[(size_t)row * DDIM + col]       = v0;
            *(float2*)&C[(size_t)(row + 8) * DDIM + col] = v1;
        }
    }
#undef LDG_CHUNK
#undef STS_CHUNK
}

__global__ __launch_bounds__(256, 1) void qkv_mma_kernel()
{
    const float* Bt = g_Wt + (size_t)blockIdx.z * DDIM * DDIM;
    float* Cp = (blockIdx.z == 0) ? g_Q : (blockIdx.z == 1) ? g_K : g_V;
    gemm_mma_body(g_x, Bt, Cp, nullptr);
}

__global__ __launch_bounds__(256, 1) void out_mma_kernel(const float* __restrict__ bo,
                                                         float* __restrict__ out)
{
    gemm_mma_body(g_ctx, g_Wt + 3ull * DDIM * DDIM, out, bo);
}

// ===========================================================================
// Causal flash attention (SIMT fp32 — proven R2 kernel, ctx tf32-rounded).
// One CTA = 64 queries x one (b,h). 256 threads.
// ===========================================================================
#define NEG_BIG (-1e30f)

__global__ __launch_bounds__(256) void attn_kernel()
{
    __shared__ float Qt[64 * 64];
    __shared__ float KtPs[64 * 64];
    __shared__ float Vs[64 * 64];

    const int tid = threadIdx.x;
    const int bh  = blockIdx.y;
    const int b   = bh >> 4;
    const int h   = bh & 15;
    const int qb  = (int)gridDim.x - 1 - (int)blockIdx.x;
    const int q0  = qb * 64;
    const int tq  = tid >> 4;
    const int tk  = tid & 15;
    const int lr  = tid >> 2;
    const int lc  = (tid & 3) << 4;
    const int lg  = lr >> 2;
    const int lq  = lr & 3;

    {
        const float* qp = g_Q + (size_t)(b * SS + q0 + lr) * DDIM + h * DHH;
#pragma unroll
        for (int i = 0; i < 4; i++) {
            const int d = lc + 4 * i;
            float4 v = *(const float4*)(qp + d);
            Qt[(d+0)*64 + (((lg + d+0) & 15) << 2) + lq] = v.x * 0.125f;
            Qt[(d+1)*64 + (((lg + d+1) & 15) << 2) + lq] = v.y * 0.125f;
            Qt[(d+2)*64 + (((lg + d+2) & 15) << 2) + lq] = v.z * 0.125f;
            Qt[(d+3)*64 + (((lg + d+3) & 15) << 2) + lq] = v.w * 0.125f;
        }
    }

    float m_i[4], l_i[4], o[4][4];
#pragma unroll
    for (int i = 0; i < 4; i++) {
        m_i[i] = NEG_BIG; l_i[i] = 0.f;
#pragma unroll
        for (int j = 0; j < 4; j++) o[i][j] = 0.f;
    }

    for (int kb = 0; kb <= qb; kb++) {
        const int k0 = kb * 64;

        __syncthreads();
        {
            const float* kp = g_K + (size_t)(b * SS + k0 + lr) * DDIM + h * DHH;
            const float* vp = g_V + (size_t)(b * SS + k0 + lr) * DDIM + h * DHH;
#pragma unroll
            for (int i = 0; i < 4; i++) {
                const int d = lc + 4 * i;
                float4 kv = *(const float4*)(kp + d);
                KtPs[(d+0)*64 + (((lg + d+0) & 15) << 2) + lq] = kv.x;
                KtPs[(d+1)*64 + (((lg + d+1) & 15) << 2) + lq] = kv.y;
                KtPs[(d+2)*64 + (((lg + d+2) & 15) << 2) + lq] = kv.z;
                KtPs[(d+3)*64 + (((lg + d+3) & 15) << 2) + lq] = kv.w;
                float4 vv = *(const float4*)(vp + d);
                *(float4*)&Vs[lr * 64 + d] = vv;
            }
        }
        __syncthreads();

        float sacc[4][4];
#pragma unroll
        for (int i = 0; i < 4; i++)
#pragma unroll
            for (int j = 0; j < 4; j++) sacc[i][j] = 0.f;

#pragma unroll 8
        for (int d = 0; d < 64; d++) {
            float4 qv = *(const float4*)&Qt[d * 64 + (((tq + d) & 15) << 2)];
            float4 kv = *(const float4*)&KtPs[d * 64 + (((tk + d) & 15) << 2)];
            float qr[4] = {qv.x, qv.y, qv.z, qv.w};
            float kr[4] = {kv.x, kv.y, kv.z, kv.w};
#pragma unroll
            for (int i = 0; i < 4; i++)
#pragma unroll
                for (int j = 0; j < 4; j++)
                    sacc[i][j] = fmaf(qr[i], kr[j], sacc[i][j]);
        }

        if (kb == qb) {
#pragma unroll
            for (int i = 0; i < 4; i++)
#pragma unroll
                for (int j = 0; j < 4; j++)
                    if (tk * 4 + j > tq * 4 + i) sacc[i][j] = NEG_BIG;
        }

        __syncthreads();

#pragma unroll
        for (int i = 0; i < 4; i++) {
            float rmax = fmaxf(fmaxf(sacc[i][0], sacc[i][1]),
                               fmaxf(sacc[i][2], sacc[i][3]));
#pragma unroll
            for (int off = 8; off >= 1; off >>= 1)
                rmax = fmaxf(rmax, __shfl_xor_sync(0xffffffffu, rmax, off));
            const float mnew = fmaxf(m_i[i], rmax);
            const float corr = __expf(m_i[i] - mnew);
            m_i[i] = mnew;
            float p[4]; float rsum = 0.f;
#pragma unroll
            for (int j = 0; j < 4; j++) { p[j] = __expf(sacc[i][j] - mnew); rsum += p[j]; }
#pragma unroll
            for (int off = 8; off >= 1; off >>= 1)
                rsum += __shfl_xor_sync(0xffffffffu, rsum, off);
            l_i[i] = l_i[i] * corr + rsum;
#pragma unroll
            for (int j = 0; j < 4; j++) {
                o[i][j] *= corr;
                const int k = tk * 4 + j;
                KtPs[k * 64 + (((tq + k) & 15) << 2) + i] = p[j];
            }
        }
        __syncthreads();

#pragma unroll 8
        for (int k = 0; k < 64; k++) {
            float4 pv = *(const float4*)&KtPs[k * 64 + (((tq + k) & 15) << 2)];
            float4 vv = *(const float4*)&Vs[k * 64 + (tk << 2)];
            float pr[4] = {pv.x, pv.y, pv.z, pv.w};
            float vr[4] = {vv.x, vv.y, vv.z, vv.w};
#pragma unroll
            for (int i = 0; i < 4; i++)
#pragma unroll
                for (int j = 0; j < 4; j++)
                    o[i][j] = fmaf(pr[i], vr[j], o[i][j]);
        }
    }

    // Epilogue: normalize, tf32-round (ctx feeds a tf32 MMA), write ctx
#pragma unroll
    for (int i = 0; i < 4; i++) {
        const float inv = 1.f / l_i[i];
        float4 v = make_float4(rna_tf32(o[i][0]*inv), rna_tf32(o[i][1]*inv),
                               rna_tf32(o[i][2]*inv), rna_tf32(o[i][3]*inv));
        *(float4*)(g_ctx + (size_t)(b * SS + q0 + tq * 4 + i) * DDIM + h * DHH + tk * 4) = v;
    }
}

// ===========================================================================
extern "C" void kernel_launch(void* const* d_in, const int* in_sizes, int n_in,
                              void* d_out, int out_size)
{
    (void)in_sizes; (void)n_in; (void)out_size;
    const float* x  = (const float*)d_in[0];
    const float* Wq = (const float*)d_in[1];
    const float* Wk = (const float*)d_in[2];
    const float* Wv = (const float*)d_in[3];
    const float* Wo = (const float*)d_in[4];
    const float* bo = (const float*)d_in[5];
    float* out = (float*)d_out;

    cudaFuncSetAttribute(qkv_mma_kernel, cudaFuncAttributeMaxDynamicSharedMemorySize,
                         GEMM_SMEM_BYTES);
    cudaFuncSetAttribute(out_mma_kernel, cudaFuncAttributeMaxDynamicSharedMemorySize,
                         GEMM_SMEM_BYTES);

    // Pre-pass: tf32 RNA rounding (+ W transpose)
    round_x_kernel<<<(MM * DDIM) / (256 * 4), 256>>>(x);
    transpose_round_kernel<<<dim3(32, 32, 4), dim3(32, 8)>>>(Wq, Wk, Wv, Wo);

    // QKV projections on tensor cores (tf32 mma.sync)
    qkv_mma_kernel<<<dim3(DDIM / GTN, MM / GTM, 3), 256, GEMM_SMEM_BYTES>>>();

    // Attention (SIMT fp32)
    attn_kernel<<<dim3(SS / 64, BB * HH), 256>>>();

    // Output projection on tensor cores
    out_mma_kernel<<<dim3(DDIM / GTN, MM / GTM), 256, GEMM_SMEM_BYTES>>>(bo, out);
}

// round 5
// speedup vs baseline: 4.0627x; 2.7926x over previous
#include <cuda_runtime.h>
#include <math.h>
#include <stdint.h>

// Problem constants
#define BB  2
#define SS  4096
#define DDIM 1024
#define HH  16
#define DHH 64
#define MM  (BB*SS)   // 8192 rows

// Scratch (allocation-free rule: __device__ globals)
__device__ float g_x[MM*DDIM];                 // tf32-rounded x
__device__ float g_Wt[4u*DDIM*DDIM];           // tf32-rounded W^T (q,k,v,o)
__device__ float g_Q[MM*DDIM];                 // tf32-rounded q (scaled later)
__device__ float g_K[MM*DDIM];                 // tf32-rounded k
__device__ float g_V[MM*DDIM];                 // tf32-rounded v
__device__ float g_ctx[MM*DDIM];               // tf32-rounded ctx

__device__ __forceinline__ float rna_tf32(float x) {
    uint32_t u;
    asm("cvt.rna.tf32.f32 %0, %1;" : "=r"(u) : "f"(x));
    return __uint_as_float(u);
}

__device__ __forceinline__ uint32_t smem_u32(const void* p) {
    uint32_t a;
    asm("{ .reg .u64 t; cvta.to.shared.u64 t, %1; cvt.u32.u64 %0, t; }"
        : "=r"(a) : "l"(p));
    return a;
}

__device__ __forceinline__ void cp_async16(uint32_t dst, const void* src) {
    asm volatile("cp.async.cg.shared.global [%0], [%1], 16;"
                 :: "r"(dst), "l"(src) : "memory");
}
#define CP_COMMIT() asm volatile("cp.async.commit_group;" ::: "memory")

#define MMA_TF32(c, a0, a1, a2, a3, b0, b1)                                    \
    asm volatile(                                                              \
        "mma.sync.aligned.m16n8k8.row.col.f32.tf32.tf32.f32 "                  \
        "{%0,%1,%2,%3},{%4,%5,%6,%7},{%8,%9},{%0,%1,%2,%3};"                   \
        : "+f"((c)[0]), "+f"((c)[1]), "+f"((c)[2]), "+f"((c)[3])               \
        : "r"(a0), "r"(a1), "r"(a2), "r"(a3), "r"(b0), "r"(b1))

// ===========================================================================
// Pre-pass kernels: tf32 RNA rounding (+ transpose for weights)
// ===========================================================================
__global__ __launch_bounds__(256) void round_x_kernel(const float* __restrict__ x)
{
    const size_t i = ((size_t)blockIdx.x * 256 + threadIdx.x) * 4;
    float4 v = *(const float4*)(x + i);
    v.x = rna_tf32(v.x); v.y = rna_tf32(v.y);
    v.z = rna_tf32(v.z); v.w = rna_tf32(v.w);
    *(float4*)(g_x + i) = v;
}

__global__ __launch_bounds__(256) void transpose_round_kernel(
    const float* __restrict__ Wq, const float* __restrict__ Wk,
    const float* __restrict__ Wv, const float* __restrict__ Wo)
{
    __shared__ float t[32][33];
    const int z = blockIdx.z;
    const float* W = (z == 0) ? Wq : (z == 1) ? Wk : (z == 2) ? Wv : Wo;
    float* Wt = g_Wt + (size_t)z * DDIM * DDIM;
    const int x0 = blockIdx.x * 32, y0 = blockIdx.y * 32;
    const int tx = threadIdx.x, ty = threadIdx.y;   // block (32,8)
#pragma unroll
    for (int i = 0; i < 4; i++) {
        const int row = ty + i * 8;
        t[row][tx] = W[(size_t)(y0 + row) * DDIM + x0 + tx];
    }
    __syncthreads();
#pragma unroll
    for (int i = 0; i < 4; i++) {
        const int row = ty + i * 8;
        Wt[(size_t)(x0 + row) * DDIM + y0 + tx] = rna_tf32(t[tx][row]);
    }
}

// ===========================================================================
// tf32 mma.sync GEMM (proven in R4): C[8192,1024] = A @ Bt^T, CTA 128x128.
// round_out: rna-round outputs (for Q/K/V which feed the attention MMA).
// ===========================================================================
#define GTM 128
#define GTN 128
#define GTK 32
#define STG_FLOATS 8192
#define GEMM_SMEM_BYTES (2 * STG_FLOATS * 4)   // 65536

__device__ __forceinline__ void gemm_mma_body(const float* __restrict__ A,
                                              const float* __restrict__ Bt,
                                              float* __restrict__ C,
                                              const float* __restrict__ bias,
                                              bool round_out)
{
    extern __shared__ float sm[];
    const int tid  = threadIdx.x;
    const int lane = tid & 31;
    const int warp = tid >> 5;
    const int wm   = warp >> 2;
    const int wn   = warp & 3;
    const int m0   = blockIdx.y * GTM;
    const int n0   = blockIdx.x * GTN;

    const int sr   = tid >> 3;
    const int kq   = tid & 7;
    const int ks_s = kq >> 1;
    const int half = kq & 1;
    const int g_s  = sr & 7;
    const int hi   = (sr >> 3) & 1;
    const int mtb  = sr >> 4;
    const int ntb  = sr >> 3;
    const int le0 = g_s * 4 + (0 ^ ks_s);
    const int le1 = g_s * 4 + (1 ^ ks_s);
    const int le2 = g_s * 4 + (2 ^ ks_s);
    const int le3 = g_s * 4 + (3 ^ ks_s);

    const float* ga = A  + (size_t)(m0 + sr) * DDIM + kq * 4;
    const float* gb = Bt + (size_t)(n0 + sr) * DDIM + kq * 4;

    float acc[16][4];
#pragma unroll
    for (int t = 0; t < 16; t++)
#pragma unroll
        for (int e = 0; e < 4; e++) acc[t][e] = 0.f;

    float4 ra[4], rb[4];

#define LDG_CHUNK(kc)                                                          \
    {                                                                          \
        _Pragma("unroll")                                                      \
        for (int i = 0; i < 4; i++) {                                          \
            ra[i] = *(const float4*)(ga + (size_t)(i * 32) * DDIM + (kc));     \
            rb[i] = *(const float4*)(gb + (size_t)(i * 32) * DDIM + (kc));     \
        }                                                                      \
    }

#define STS_CHUNK(s)                                                           \
    {                                                                          \
        float* sAp = sm + (s) * STG_FLOATS;                                    \
        float* sBp = sAp + 4096;                                               \
        _Pragma("unroll")                                                      \
        for (int i = 0; i < 4; i++) {                                          \
            float* da = sAp + (ks_s * 8 + i * 2 + mtb) * 128 + half * 2 + hi;  \
            da[le0 * 4] = ra[i].x;                                             \
            da[le1 * 4] = ra[i].y;                                             \
            da[le2 * 4] = ra[i].z;                                             \
            da[le3 * 4] = ra[i].w;                                             \
            float* db = sBp + (ks_s * 16 + i * 4 + ntb) * 64 + half;           \
            db[le0 * 2] = rb[i].x;                                             \
            db[le1 * 2] = rb[i].y;                                             \
            db[le2 * 2] = rb[i].z;                                             \
            db[le3 * 2] = rb[i].w;                                             \
        }                                                                      \
    }

    LDG_CHUNK(0);
    STS_CHUNK(0);
    __syncthreads();

    for (int it = 0; it < 32; ++it) {
        if (it < 31) LDG_CHUNK((it + 1) * GTK);

        const float* sAc = sm + (it & 1) * STG_FLOATS;
        const float* sBc = sAc + 4096;

#pragma unroll
        for (int ks = 0; ks < 4; ks++) {
            const int lsw = lane ^ ks;
            uint32_t af[4][4];
            uint32_t bf[4][2];
#pragma unroll
            for (int i = 0; i < 4; i++) {
                float4 av = *(const float4*)&sAc[((ks * 8 + wm * 4 + i) * 32 + lsw) * 4];
                af[i][0] = __float_as_uint(av.x);
                af[i][1] = __float_as_uint(av.y);
                af[i][2] = __float_as_uint(av.z);
                af[i][3] = __float_as_uint(av.w);
            }
#pragma unroll
            for (int j = 0; j < 4; j++) {
                float2 bv = *(const float2*)&sBc[((ks * 16 + wn * 4 + j) * 32 + lsw) * 2];
                bf[j][0] = __float_as_uint(bv.x);
                bf[j][1] = __float_as_uint(bv.y);
            }
#pragma unroll
            for (int i = 0; i < 4; i++)
#pragma unroll
                for (int j = 0; j < 4; j++)
                    MMA_TF32(acc[i * 4 + j],
                             af[i][0], af[i][1], af[i][2], af[i][3],
                             bf[j][0], bf[j][1]);
        }

        if (it < 31) STS_CHUNK((it + 1) & 1);
        __syncthreads();
    }

    const int g   = lane >> 2;
    const int cth = lane & 3;
#pragma unroll
    for (int i = 0; i < 4; i++) {
        const int row = m0 + wm * 64 + i * 16 + g;
#pragma unroll
        for (int j = 0; j < 4; j++) {
            const int col = n0 + wn * 32 + j * 8 + cth * 2;
            float2 v0 = make_float2(acc[i * 4 + j][0], acc[i * 4 + j][1]);
            float2 v1 = make_float2(acc[i * 4 + j][2], acc[i * 4 + j][3]);
            if (bias != nullptr) {
                const float b0 = bias[col], b1 = bias[col + 1];
                v0.x += b0; v0.y += b1;
                v1.x += b0; v1.y += b1;
            }
            if (round_out) {
                v0.x = rna_tf32(v0.x); v0.y = rna_tf32(v0.y);
                v1.x = rna_tf32(v1.x); v1.y = rna_tf32(v1.y);
            }
            *(float2*)&C[(size_t)row * DDIM + col]       = v0;
            *(float2*)&C[(size_t)(row + 8) * DDIM + col] = v1;
        }
    }
#undef LDG_CHUNK
#undef STS_CHUNK
}

__global__ __launch_bounds__(256, 1) void qkv_mma_kernel()
{
    const float* Bt = g_Wt + (size_t)blockIdx.z * DDIM * DDIM;
    float* Cp = (blockIdx.z == 0) ? g_Q : (blockIdx.z == 1) ? g_K : g_V;
    gemm_mma_body(g_x, Bt, Cp, nullptr, true);
}

__global__ __launch_bounds__(256, 1) void out_mma_kernel(const float* __restrict__ bo,
                                                         float* __restrict__ out)
{
    gemm_mma_body(g_ctx, g_Wt + 3ull * DDIM * DDIM, out, bo, false);
}

// ===========================================================================
// tf32 mma.sync causal flash attention.
// CTA: 128 queries x one (b,h), 256 threads (8 warps x 16 q-rows).
// K-block = 64 keys. K/V staged row-major stride 68 (conflict-free scalar
// B-frag LDS), cp.async double-buffered. Q held in registers as A-frags.
// S C-frags -> P A-frags via quad shuffles (no smem round trip).
// ===========================================================================
#define NEG_BIG (-1e30f)
#define AT_STRIDE 68
#define AT_TILE_F (64 * AT_STRIDE)          // 4352 floats = 17408 B
#define AT_STAGE_F (2 * AT_TILE_F)          // K + V per stage
#define ATT_SMEM_BYTES (2 * AT_STAGE_F * 4) // 69632

__global__ __launch_bounds__(256, 1) void attn_mma_kernel()
{
    extern __shared__ float smf[];
    const uint32_t sb = smem_u32(smf);
    const int tid = threadIdx.x, lane = tid & 31, warp = tid >> 5;
    const int bh = blockIdx.y, b = bh >> 4, h = bh & 15;
    const int qt = (int)gridDim.x - 1 - (int)blockIdx.x;   // heavy first
    const int q0 = qt * 128;
    const int qw0 = q0 + warp * 16;
    const int nb = 2 * qt + 2;
    const int r = lane >> 2, c = lane & 3;

    const float* gq  = g_Q + (size_t)(b * SS + q0) * DDIM + h * DHH;
    const float* gk0 = g_K + (size_t)(b * SS) * DDIM + h * DHH;
    const float* gv0 = g_V + (size_t)(b * SS) * DDIM + h * DHH;

    // ---- stage Q (128 x 64) into stage-0 region, then load A-frags ----
#pragma unroll
    for (int i = 0; i < 8; i++) {
        const int ch = tid + i * 256;
        const int row = ch >> 4, c16 = ch & 15;
        cp_async16(sb + row * 272 + c16 * 16, gq + (size_t)row * DDIM + c16 * 4);
    }
    CP_COMMIT();
    asm volatile("cp.async.wait_group 0;" ::: "memory");
    __syncthreads();

    uint32_t qa[8][4];
#pragma unroll
    for (int ks = 0; ks < 8; ks++) {
        const float* qs = smf + (warp * 16 + r) * AT_STRIDE + ks * 8 + c;
        qa[ks][0] = __float_as_uint(qs[0] * 0.125f);
        qa[ks][1] = __float_as_uint(qs[8 * AT_STRIDE] * 0.125f);
        qa[ks][2] = __float_as_uint(qs[4] * 0.125f);
        qa[ks][3] = __float_as_uint(qs[8 * AT_STRIDE + 4] * 0.125f);
    }
    __syncthreads();

    float O[8][4];
#pragma unroll
    for (int t = 0; t < 8; t++)
#pragma unroll
        for (int e = 0; e < 4; e++) O[t][e] = 0.f;
    float m0v = NEG_BIG, m1v = NEG_BIG, l0v = 0.f, l1v = 0.f;

#define AT_ISSUE(kb, s)                                                            \
    {                                                                              \
        const float* gk = gk0 + (size_t)(kb) * 64 * DDIM;                          \
        const float* gv = gv0 + (size_t)(kb) * 64 * DDIM;                          \
        const uint32_t db = sb + (uint32_t)(s) * (AT_STAGE_F * 4);                 \
        _Pragma("unroll")                                                          \
        for (int i = 0; i < 4; i++) {                                              \
            const int ch = tid + i * 256;                                          \
            const int row = ch >> 4, c16 = ch & 15;                                \
            cp_async16(db + row * 272 + c16 * 16, gk + (size_t)row * DDIM + c16 * 4); \
            cp_async16(db + (AT_TILE_F * 4) + row * 272 + c16 * 16,                \
                       gv + (size_t)row * DDIM + c16 * 4);                         \
        }                                                                          \
    }

    AT_ISSUE(0, 0);
    CP_COMMIT();

    const int l0p = (lane & 28) | ((lane & 3) >> 1);
    const int l2p = l0p + 2;
    const bool odd = (lane & 1) != 0;

    for (int kb = 0; kb < nb; kb++) {
        if (kb + 1 < nb) {
            AT_ISSUE(kb + 1, (kb + 1) & 1);
            CP_COMMIT();
            asm volatile("cp.async.wait_group 1;" ::: "memory");
        } else {
            asm volatile("cp.async.wait_group 0;" ::: "memory");
        }
        __syncthreads();

        const int k0 = kb * 64;
        if (k0 <= qw0 + 15) {                       // else fully masked: skip
            const float* Ksm = smf + (kb & 1) * AT_STAGE_F;
            const float* Vsm = Ksm + AT_TILE_F;

            // ---- S = Q K^T ----
            float s[8][4];
#pragma unroll
            for (int t = 0; t < 8; t++)
#pragma unroll
                for (int e = 0; e < 4; e++) s[t][e] = 0.f;

#pragma unroll
            for (int ks = 0; ks < 8; ks++) {
#pragma unroll
                for (int nt = 0; nt < 8; nt++) {
                    const float* kp = Ksm + (nt * 8 + r) * AT_STRIDE + ks * 8 + c;
                    const uint32_t b0 = __float_as_uint(kp[0]);
                    const uint32_t b1 = __float_as_uint(kp[4]);
                    MMA_TF32(s[nt], qa[ks][0], qa[ks][1], qa[ks][2], qa[ks][3], b0, b1);
                }
            }

            // ---- causal mask (only near the diagonal) ----
            if (k0 + 63 > qw0) {
                const int qlo = qw0 + r, qhi = qlo + 8;
#pragma unroll
                for (int nt = 0; nt < 8; nt++) {
                    const int key0 = k0 + nt * 8 + 2 * c;
                    if (key0     > qlo) s[nt][0] = NEG_BIG;
                    if (key0 + 1 > qlo) s[nt][1] = NEG_BIG;
                    if (key0     > qhi) s[nt][2] = NEG_BIG;
                    if (key0 + 1 > qhi) s[nt][3] = NEG_BIG;
                }
            }

            // ---- online softmax ----
            float cl = NEG_BIG, chv = NEG_BIG;
#pragma unroll
            for (int nt = 0; nt < 8; nt++) {
                cl  = fmaxf(cl,  fmaxf(s[nt][0], s[nt][1]));
                chv = fmaxf(chv, fmaxf(s[nt][2], s[nt][3]));
            }
            cl  = fmaxf(cl,  __shfl_xor_sync(0xffffffffu, cl, 1));
            cl  = fmaxf(cl,  __shfl_xor_sync(0xffffffffu, cl, 2));
            chv = fmaxf(chv, __shfl_xor_sync(0xffffffffu, chv, 1));
            chv = fmaxf(chv, __shfl_xor_sync(0xffffffffu, chv, 2));
            const float mn0 = fmaxf(m0v, cl), mn1 = fmaxf(m1v, chv);
            const float corr0 = __expf(m0v - mn0), corr1 = __expf(m1v - mn1);
            m0v = mn0; m1v = mn1;

            float sl = 0.f, sh = 0.f;
#pragma unroll
            for (int nt = 0; nt < 8; nt++) {
                s[nt][0] = __expf(s[nt][0] - mn0); sl += s[nt][0];
                s[nt][1] = __expf(s[nt][1] - mn0); sl += s[nt][1];
                s[nt][2] = __expf(s[nt][2] - mn1); sh += s[nt][2];
                s[nt][3] = __expf(s[nt][3] - mn1); sh += s[nt][3];
            }
            sl += __shfl_xor_sync(0xffffffffu, sl, 1);
            sl += __shfl_xor_sync(0xffffffffu, sl, 2);
            sh += __shfl_xor_sync(0xffffffffu, sh, 1);
            sh += __shfl_xor_sync(0xffffffffu, sh, 2);
            l0v = l0v * corr0 + sl;
            l1v = l1v * corr1 + sh;

#pragma unroll
            for (int nt = 0; nt < 8; nt++) {
                O[nt][0] *= corr0; O[nt][1] *= corr0;
                O[nt][2] *= corr1; O[nt][3] *= corr1;
                s[nt][0] = rna_tf32(s[nt][0]); s[nt][1] = rna_tf32(s[nt][1]);
                s[nt][2] = rna_tf32(s[nt][2]); s[nt][3] = rna_tf32(s[nt][3]);
            }

            // ---- O += P V : shuffle C-frags -> A-frags, then mma ----
#pragma unroll
            for (int ks = 0; ks < 8; ks++) {
                const float e0 = __shfl_sync(0xffffffffu, s[ks][0], l0p);
                const float o0 = __shfl_sync(0xffffffffu, s[ks][1], l0p);
                const float e2 = __shfl_sync(0xffffffffu, s[ks][0], l2p);
                const float o2 = __shfl_sync(0xffffffffu, s[ks][1], l2p);
                const float e1 = __shfl_sync(0xffffffffu, s[ks][2], l0p);
                const float o1 = __shfl_sync(0xffffffffu, s[ks][3], l0p);
                const float e3 = __shfl_sync(0xffffffffu, s[ks][2], l2p);
                const float o3 = __shfl_sync(0xffffffffu, s[ks][3], l2p);
                const uint32_t a0 = __float_as_uint(odd ? o0 : e0);
                const uint32_t a1 = __float_as_uint(odd ? o1 : e1);
                const uint32_t a2 = __float_as_uint(odd ? o2 : e2);
                const uint32_t a3 = __float_as_uint(odd ? o3 : e3);
#pragma unroll
                for (int nt = 0; nt < 8; nt++) {
                    const float* vp = Vsm + (ks * 8 + c) * AT_STRIDE + nt * 8 + r;
                    const uint32_t b0 = __float_as_uint(vp[0]);
                    const uint32_t b1 = __float_as_uint(vp[4 * AT_STRIDE]);
                    MMA_TF32(O[nt], a0, a1, a2, a3, b0, b1);
                }
            }
        }
        __syncthreads();
    }

    // ---- epilogue: normalize, rna-round (feeds tf32 out-proj), store ----
    const float inv0 = 1.f / l0v, inv1 = 1.f / l1v;
    const size_t row0 = (size_t)(b * SS + qw0 + r);
#pragma unroll
    for (int nt = 0; nt < 8; nt++) {
        const int col = h * DHH + nt * 8 + 2 * c;
        float2 w0 = make_float2(rna_tf32(O[nt][0] * inv0), rna_tf32(O[nt][1] * inv0));
        float2 w1 = make_float2(rna_tf32(O[nt][2] * inv1), rna_tf32(O[nt][3] * inv1));
        *(float2*)&g_ctx[row0 * DDIM + col]       = w0;
        *(float2*)&g_ctx[(row0 + 8) * DDIM + col] = w1;
    }
#undef AT_ISSUE
}

// ===========================================================================
extern "C" void kernel_launch(void* const* d_in, const int* in_sizes, int n_in,
                              void* d_out, int out_size)
{
    (void)in_sizes; (void)n_in; (void)out_size;
    const float* x  = (const float*)d_in[0];
    const float* Wq = (const float*)d_in[1];
    const float* Wk = (const float*)d_in[2];
    const float* Wv = (const float*)d_in[3];
    const float* Wo = (const float*)d_in[4];
    const float* bo = (const float*)d_in[5];
    float* out = (float*)d_out;

    cudaFuncSetAttribute(qkv_mma_kernel, cudaFuncAttributeMaxDynamicSharedMemorySize,
                         GEMM_SMEM_BYTES);
    cudaFuncSetAttribute(out_mma_kernel, cudaFuncAttributeMaxDynamicSharedMemorySize,
                         GEMM_SMEM_BYTES);
    cudaFuncSetAttribute(attn_mma_kernel, cudaFuncAttributeMaxDynamicSharedMemorySize,
                         ATT_SMEM_BYTES);

    round_x_kernel<<<(MM * DDIM) / (256 * 4), 256>>>(x);
    transpose_round_kernel<<<dim3(32, 32, 4), dim3(32, 8)>>>(Wq, Wk, Wv, Wo);

    qkv_mma_kernel<<<dim3(DDIM / GTN, MM / GTM, 3), 256, GEMM_SMEM_BYTES>>>();

    attn_mma_kernel<<<dim3(SS / 128, BB * HH), 256, ATT_SMEM_BYTES>>>();

    out_mma_kernel<<<dim3(DDIM / GTN, MM / GTM), 256, GEMM_SMEM_BYTES>>>(bo, out);
}